// round 7
// baseline (speedup 1.0000x reference)
#include <cuda_runtime.h>
#include <cuda_bf16.h>

#define N_NODES 50000
#define D 16
#define H 64

__device__ float g_acc[N_NODES * D];
__device__ float g_deg[N_NODES];
// Per-node first-layer partials: [n][0:64)=P=W1a@x[n], [n][64:128)=Q=W1b@x[n]
__device__ float g_PQ[N_NODES * 2 * H];

__global__ void init_kernel() {
    int idx = blockIdx.x * blockDim.x + threadIdx.x;
    int total = N_NODES * D + N_NODES;
    if (idx < N_NODES * D) {
        g_acc[idx] = 0.0f;
    } else if (idx < total) {
        g_deg[idx - N_NODES * D] = 0.0f;
    }
}

__global__ void deg_kernel(const int* __restrict__ ei, int E) {
    int e = blockIdx.x * blockDim.x + threadIdx.x;
    if (e >= E) return;
    atomicAdd(&g_deg[ei[e]], 1.0f);
    atomicAdd(&g_deg[ei[E + e]], 1.0f);
}

__global__ __launch_bounds__(128)
void node_kernel(const float* __restrict__ x, const float* __restrict__ W1, int n_nodes)
{
    __shared__ float w1s[H * 32];
    for (int i = threadIdx.x; i < H * 32; i += blockDim.x) w1s[i] = W1[i];
    __syncthreads();

    int n = blockIdx.x * blockDim.x + threadIdx.x;
    if (n >= n_nodes) return;

    float xv[D];
    const float4* px = (const float4*)(x + (size_t)n * D);
#pragma unroll
    for (int q = 0; q < 4; q++) {
        float4 v4 = px[q];
        xv[4 * q + 0] = v4.x; xv[4 * q + 1] = v4.y;
        xv[4 * q + 2] = v4.z; xv[4 * q + 3] = v4.w;
    }

    float* pq = &g_PQ[(size_t)n * 2 * H];
#pragma unroll 4
    for (int jg = 0; jg < H / 4; jg++) {
        float p[4], qv[4];
#pragma unroll
        for (int jj = 0; jj < 4; jj++) {
            const float* w = &w1s[(jg * 4 + jj) * 32];
            float p0 = 0.f, p1 = 0.f, q0 = 0.f, q1 = 0.f;
#pragma unroll
            for (int k = 0; k < D; k += 2) {
                p0 = fmaf(w[k],          xv[k],     p0);
                p1 = fmaf(w[k + 1],      xv[k + 1], p1);
                q0 = fmaf(w[16 + k],     xv[k],     q0);
                q1 = fmaf(w[16 + k + 1], xv[k + 1], q1);
            }
            p[jj] = p0 + p1;
            qv[jj] = q0 + q1;
        }
        *(float4*)(pq + jg * 4)     = make_float4(p[0], p[1], p[2], p[3]);
        *(float4*)(pq + H + jg * 4) = make_float4(qv[0], qv[1], qv[2], qv[3]);
    }
}

__device__ __forceinline__ void red_add_v4(float* addr, float a, float b, float c, float d) {
    asm volatile("red.global.add.v4.f32 [%0], {%1, %2, %3, %4};"
                 :: "l"(addr), "f"(a), "f"(b), "f"(c), "f"(d) : "memory");
}

__device__ __forceinline__ float relu_(float v) { return fmaxf(v, 0.0f); }

// 4 threads per edge. Thread t of an edge:
//  - loads PQ float4-chunks c = 4k + t  (lanes of an edge contiguous per instruction)
//  - computes layer-2 partials for those 16 hidden units into pu/pw[16]
//  - butterfly-reduces so it ends owning output dims [4t, 4t+4)
//  - cooperative dots via 7-scalar shuffle reduce, then writes its 4 dims.
__global__ __launch_bounds__(256)
void edge_kernel(const float* __restrict__ x, const int* __restrict__ ei,
                 const float* __restrict__ b1, const float* __restrict__ W2,
                 const float* __restrict__ b2, int E)
{
    __shared__ __align__(16) float w2ts[H * D];   // w2ts[j][i] = W2[i][j]
    __shared__ __align__(16) float b1s[H];
    __shared__ float b2s[D];

    for (int i = threadIdx.x; i < H * D; i += blockDim.x) {
        int j = i / D, ii = i % D;
        w2ts[i] = W2[ii * H + j];
    }
    if (threadIdx.x < H) b1s[threadIdx.x] = b1[threadIdx.x];
    if (threadIdx.x < D) b2s[threadIdx.x] = b2[threadIdx.x];
    __syncthreads();

    int lane = threadIdx.x & 31;
    int t = lane & 3;
    int gwarp = (blockIdx.x * blockDim.x + threadIdx.x) >> 5;
    int e = gwarp * 8 + (lane >> 2);
    bool valid = (e < E);
    if (e >= E) e = E - 1;                 // clamp: keep warp uniform for shuffles

    int s = ei[e];
    int d = ei[E + e];

    const float4* Ps = (const float4*)&g_PQ[(size_t)s * 2 * H];
    const float4* Qs = Ps + H / 4;
    const float4* Pd = (const float4*)&g_PQ[(size_t)d * 2 * H];
    const float4* Qd = Pd + H / 4;
    const float4* b1v = (const float4*)b1s;

    float pu[16], pw[16];
#pragma unroll
    for (int i = 0; i < 16; i++) { pu[i] = 0.f; pw[i] = 0.f; }

#pragma unroll
    for (int k = 0; k < 4; k++) {
        int c = (k << 2) + t;              // float4 chunk of H owned this iter
        float4 ps = Ps[c], qd = Qd[c], pd = Pd[c], qs = Qs[c];
        float4 bb = b1v[c];
        float hu[4], hw[4];
        hu[0] = relu_(ps.x + qd.x + bb.x);
        hu[1] = relu_(ps.y + qd.y + bb.y);
        hu[2] = relu_(ps.z + qd.z + bb.z);
        hu[3] = relu_(ps.w + qd.w + bb.w);
        hw[0] = relu_(pd.x + qs.x + bb.x);
        hw[1] = relu_(pd.y + qs.y + bb.y);
        hw[2] = relu_(pd.z + qs.z + bb.z);
        hw[3] = relu_(pd.w + qs.w + bb.w);
#pragma unroll
        for (int jj = 0; jj < 4; jj++) {
            const float4* w2v = (const float4*)&w2ts[(4 * c + jj) * D];
            float4 w0 = w2v[0], w1 = w2v[1], w2q = w2v[2], w3 = w2v[3];
            float a = hu[jj], b = hw[jj];
            pu[0]  = fmaf(w0.x, a, pu[0]);  pw[0]  = fmaf(w0.x, b, pw[0]);
            pu[1]  = fmaf(w0.y, a, pu[1]);  pw[1]  = fmaf(w0.y, b, pw[1]);
            pu[2]  = fmaf(w0.z, a, pu[2]);  pw[2]  = fmaf(w0.z, b, pw[2]);
            pu[3]  = fmaf(w0.w, a, pu[3]);  pw[3]  = fmaf(w0.w, b, pw[3]);
            pu[4]  = fmaf(w1.x, a, pu[4]);  pw[4]  = fmaf(w1.x, b, pw[4]);
            pu[5]  = fmaf(w1.y, a, pu[5]);  pw[5]  = fmaf(w1.y, b, pw[5]);
            pu[6]  = fmaf(w1.z, a, pu[6]);  pw[6]  = fmaf(w1.z, b, pw[6]);
            pu[7]  = fmaf(w1.w, a, pu[7]);  pw[7]  = fmaf(w1.w, b, pw[7]);
            pu[8]  = fmaf(w2q.x, a, pu[8]); pw[8]  = fmaf(w2q.x, b, pw[8]);
            pu[9]  = fmaf(w2q.y, a, pu[9]); pw[9]  = fmaf(w2q.y, b, pw[9]);
            pu[10] = fmaf(w2q.z, a, pu[10]); pw[10] = fmaf(w2q.z, b, pw[10]);
            pu[11] = fmaf(w2q.w, a, pu[11]); pw[11] = fmaf(w2q.w, b, pw[11]);
            pu[12] = fmaf(w3.x, a, pu[12]); pw[12] = fmaf(w3.x, b, pw[12]);
            pu[13] = fmaf(w3.y, a, pu[13]); pw[13] = fmaf(w3.y, b, pw[13]);
            pu[14] = fmaf(w3.z, a, pu[14]); pw[14] = fmaf(w3.z, b, pw[14]);
            pu[15] = fmaf(w3.w, a, pu[15]); pw[15] = fmaf(w3.w, b, pw[15]);
        }
    }

    // ---- reduction round 1 (xor 2): keep 8 dims ----
    float qu[8], qw[8];
    {
        float ru[16], rw[16];
#pragma unroll
        for (int i = 0; i < 16; i++) {
            ru[i] = __shfl_xor_sync(0xffffffffu, pu[i], 2);
            rw[i] = __shfl_xor_sync(0xffffffffu, pw[i], 2);
        }
        if ((lane & 2) == 0) {
#pragma unroll
            for (int i = 0; i < 8; i++) { qu[i] = pu[i] + ru[i]; qw[i] = pw[i] + rw[i]; }
        } else {
#pragma unroll
            for (int i = 0; i < 8; i++) { qu[i] = pu[i + 8] + ru[i + 8]; qw[i] = pw[i + 8] + rw[i + 8]; }
        }
    }
    // ---- reduction round 2 (xor 1): keep 4 dims -> thread t owns dims [4t,4t+4) ----
    float fu[4], fw[4];
    {
        float ru[8], rw[8];
#pragma unroll
        for (int i = 0; i < 8; i++) {
            ru[i] = __shfl_xor_sync(0xffffffffu, qu[i], 1);
            rw[i] = __shfl_xor_sync(0xffffffffu, qw[i], 1);
        }
        if ((lane & 1) == 0) {
#pragma unroll
            for (int i = 0; i < 4; i++) { fu[i] = qu[i] + ru[i]; fw[i] = qw[i] + rw[i]; }
        } else {
#pragma unroll
            for (int i = 0; i < 4; i++) { fu[i] = qu[i + 4] + ru[i + 4]; fw[i] = qw[i + 4] + rw[i + 4]; }
        }
    }
    // add b2 once (per owned dim)
#pragma unroll
    for (int i = 0; i < 4; i++) {
        float b2i = b2s[4 * t + i];
        fu[i] += b2i;
        fw[i] += b2i;
    }

    // own slice of x
    float xso[4], xdo[4];
    {
        float4 a = *(const float4*)(x + (size_t)s * D + 4 * t);
        float4 b = *(const float4*)(x + (size_t)d * D + 4 * t);
        xso[0] = a.x; xso[1] = a.y; xso[2] = a.z; xso[3] = a.w;
        xdo[0] = b.x; xdo[1] = b.y; xdo[2] = b.z; xdo[3] = b.w;
    }

    // 7 partial dots over own dims
    float n2u = 0.f, n2w = 0.f, puw = 0.f, pu_xd = 0.f, pw_xd = 0.f, pu_xs = 0.f, pw_xs = 0.f;
#pragma unroll
    for (int i = 0; i < 4; i++) {
        n2u   = fmaf(fu[i], fu[i],  n2u);
        n2w   = fmaf(fw[i], fw[i],  n2w);
        puw   = fmaf(fu[i], fw[i],  puw);
        pu_xd = fmaf(fu[i], xdo[i], pu_xd);
        pw_xd = fmaf(fw[i], xdo[i], pw_xd);
        pu_xs = fmaf(fu[i], xso[i], pu_xs);
        pw_xs = fmaf(fw[i], xso[i], pw_xs);
    }
#pragma unroll
    for (int m = 1; m <= 2; m <<= 1) {
        n2u   += __shfl_xor_sync(0xffffffffu, n2u,   m);
        n2w   += __shfl_xor_sync(0xffffffffu, n2w,   m);
        puw   += __shfl_xor_sync(0xffffffffu, puw,   m);
        pu_xd += __shfl_xor_sync(0xffffffffu, pu_xd, m);
        pw_xd += __shfl_xor_sync(0xffffffffu, pw_xd, m);
        pu_xs += __shfl_xor_sync(0xffffffffu, pu_xs, m);
        pw_xs += __shfl_xor_sync(0xffffffffu, pw_xs, m);
    }

    float invu = 1.0f / fmaxf(sqrtf(n2u), 1e-12f);
    float invw = 1.0f / fmaxf(sqrtf(n2w), 1e-12f);

    float uw   = puw   * invu * invw;
    float u_xd = pu_xd * invu;
    float w_xd = pw_xd * invw;
    float u_xs = pu_xs * invu;
    float w_xs = pw_xs * invw;

    float coef = rsqrtf(fmaxf(g_deg[s], 1e-5f)) * rsqrtf(fmaxf(g_deg[d], 1e-5f));

    // F_s = I-2uu^T, F_d = I-2ww^T, L = -F_s^T F_d
    float cu_s = (-2.0f * u_xd + 4.0f * uw * w_xd) * invu;  // coefficient on raw fu
    float cw_s = (-2.0f * w_xd) * invw;                     // coefficient on raw fw
    float cu_d = (-2.0f * u_xs) * invu;
    float cw_d = (-2.0f * w_xs + 4.0f * uw * u_xs) * invw;

    if (valid) {
        float ms[4], md[4];
#pragma unroll
        for (int i = 0; i < 4; i++) {
            ms[i] = -coef * (xdo[i] + cu_s * fu[i] + cw_s * fw[i]);
            md[i] = -coef * (xso[i] + cu_d * fu[i] + cw_d * fw[i]);
        }
        red_add_v4(&g_acc[(size_t)s * D + 4 * t], ms[0], ms[1], ms[2], ms[3]);
        red_add_v4(&g_acc[(size_t)d * D + 4 * t], md[0], md[1], md[2], md[3]);
    }
}

__global__ void out_kernel(const float* __restrict__ x, float* __restrict__ out, int n) {
    int idx = blockIdx.x * blockDim.x + threadIdx.x;
    if (idx >= n) return;
    out[idx] = fmaxf(x[idx] - g_acc[idx], 0.0f);
}

extern "C" void kernel_launch(void* const* d_in, const int* in_sizes, int n_in,
                              void* d_out, int out_size) {
    const float* x  = (const float*)d_in[0];
    const int*   ei = (const int*)d_in[1];   // edge_index is int32 (JAX x64 disabled)
    const float* W1 = (const float*)d_in[2];
    const float* b1 = (const float*)d_in[3];
    const float* W2 = (const float*)d_in[4];
    const float* b2 = (const float*)d_in[5];
    float* out = (float*)d_out;

    int E = in_sizes[1] / 2;
    int n = in_sizes[0];
    int n_nodes = n / D;

    int initTotal = N_NODES * D + N_NODES;
    init_kernel<<<(initTotal + 255) / 256, 256>>>();
    deg_kernel<<<(E + 255) / 256, 256>>>(ei, E);
    node_kernel<<<(n_nodes + 127) / 128, 128>>>(x, W1, n_nodes);

    // 4 threads per edge, 8 edges per warp, 64 edges per 256-thread block
    int blocks = (E + 63) / 64;
    edge_kernel<<<blocks, 256>>>(x, ei, b1, W2, b2, E);

    out_kernel<<<(n + 255) / 256, 256>>>(x, out, n);
}

// round 8
// speedup vs baseline: 1.9210x; 1.9210x over previous
#include <cuda_runtime.h>
#include <cuda_bf16.h>

#define N_NODES 50000
#define D 16
#define H 64

__device__ float g_acc[N_NODES * D];
__device__ float g_deg[N_NODES];
// Per-node first-layer partials: [n][0:64)=P=W1a@x[n], [n][64:128)=Q=W1b@x[n]
__device__ float g_PQ[N_NODES * 2 * H];

__global__ void init_kernel() {
    int idx = blockIdx.x * blockDim.x + threadIdx.x;
    int total = N_NODES * D + N_NODES;
    if (idx < N_NODES * D) {
        g_acc[idx] = 0.0f;
    } else if (idx < total) {
        g_deg[idx - N_NODES * D] = 0.0f;
    }
}

__global__ void deg_kernel(const int* __restrict__ ei, int E) {
    int e = blockIdx.x * blockDim.x + threadIdx.x;
    if (e >= E) return;
    atomicAdd(&g_deg[ei[e]], 1.0f);
    atomicAdd(&g_deg[ei[E + e]], 1.0f);
}

__global__ __launch_bounds__(128)
void node_kernel(const float* __restrict__ x, const float* __restrict__ W1, int n_nodes)
{
    __shared__ float w1s[H * 32];
    for (int i = threadIdx.x; i < H * 32; i += blockDim.x) w1s[i] = W1[i];
    __syncthreads();

    int n = blockIdx.x * blockDim.x + threadIdx.x;
    if (n >= n_nodes) return;

    float xv[D];
    const float4* px = (const float4*)(x + (size_t)n * D);
#pragma unroll
    for (int q = 0; q < 4; q++) {
        float4 v4 = px[q];
        xv[4 * q + 0] = v4.x; xv[4 * q + 1] = v4.y;
        xv[4 * q + 2] = v4.z; xv[4 * q + 3] = v4.w;
    }

    float* pq = &g_PQ[(size_t)n * 2 * H];
#pragma unroll 4
    for (int jg = 0; jg < H / 4; jg++) {
        float p[4], qv[4];
#pragma unroll
        for (int jj = 0; jj < 4; jj++) {
            const float* w = &w1s[(jg * 4 + jj) * 32];
            float p0 = 0.f, p1 = 0.f, q0 = 0.f, q1 = 0.f;
#pragma unroll
            for (int k = 0; k < D; k += 2) {
                p0 = fmaf(w[k],          xv[k],     p0);
                p1 = fmaf(w[k + 1],      xv[k + 1], p1);
                q0 = fmaf(w[16 + k],     xv[k],     q0);
                q1 = fmaf(w[16 + k + 1], xv[k + 1], q1);
            }
            p[jj] = p0 + p1;
            qv[jj] = q0 + q1;
        }
        *(float4*)(pq + jg * 4)     = make_float4(p[0], p[1], p[2], p[3]);
        *(float4*)(pq + H + jg * 4) = make_float4(qv[0], qv[1], qv[2], qv[3]);
    }
}

__device__ __forceinline__ void red_add_v4(float* addr, float a, float b, float c, float d) {
    asm volatile("red.global.add.v4.f32 [%0], {%1, %2, %3, %4};"
                 :: "l"(addr), "f"(a), "f"(b), "f"(c), "f"(d) : "memory");
}

__device__ __forceinline__ float relu_(float v) { return fmaxf(v, 0.0f); }

// 4 threads per edge, 8 edges per warp.
// W2 is stored permuted in shared as [k][jj][ic][t] float4-chunks so that the
// 4 lanes of a quad (t=0..3) always read contiguous 64B -> conflict-free LDS.
__global__ __launch_bounds__(256, 3)
void edge_kernel(const float* __restrict__ x, const int* __restrict__ ei,
                 const float* __restrict__ b1, const float* __restrict__ W2,
                 const float* __restrict__ b2, int E)
{
    __shared__ __align__(16) float w2p[H * D];
    __shared__ __align__(16) float b1s[H];
    __shared__ float b2s[D];

    // Permuted store: row j = 16k + 4t + jj, dim i = 4*ic + ii
    // p = (((k*4 + jj)*4 + ic)*4 + t)*4 + ii
    for (int idx = threadIdx.x; idx < H * D; idx += blockDim.x) {
        int j = idx >> 4, i = idx & 15;
        int k = j >> 4, t = (j >> 2) & 3, jj = j & 3;
        int ic = i >> 2, ii = i & 3;
        int p = (((k * 4 + jj) * 4 + ic) * 4 + t) * 4 + ii;
        w2p[p] = W2[i * H + j];
    }
    if (threadIdx.x < H) b1s[threadIdx.x] = b1[threadIdx.x];
    if (threadIdx.x < D) b2s[threadIdx.x] = b2[threadIdx.x];
    __syncthreads();

    int lane = threadIdx.x & 31;
    int t = lane & 3;
    int gwarp = (blockIdx.x * blockDim.x + threadIdx.x) >> 5;
    int e = gwarp * 8 + (lane >> 2);
    bool valid = (e < E);
    if (e >= E) e = E - 1;                 // clamp: keep warp uniform for shuffles

    int s = ei[e];
    int d = ei[E + e];

    const float4* Ps = (const float4*)&g_PQ[(size_t)s * 2 * H];
    const float4* Qs = Ps + H / 4;
    const float4* Pd = (const float4*)&g_PQ[(size_t)d * 2 * H];
    const float4* Qd = Pd + H / 4;
    const float4* b1v = (const float4*)b1s;
    const float4* w2v4 = (const float4*)w2p;

    float pu[16], pw[16];
#pragma unroll
    for (int i = 0; i < 16; i++) { pu[i] = 0.f; pw[i] = 0.f; }

#pragma unroll
    for (int k = 0; k < 4; k++) {
        int c = (k << 2) + t;              // float4 chunk of H owned this iter
        float4 ps = Ps[c], qd = Qd[c], pd = Pd[c], qs = Qs[c];
        float4 bb = b1v[c];
        float hu[4], hw[4];
        hu[0] = relu_(ps.x + qd.x + bb.x);
        hu[1] = relu_(ps.y + qd.y + bb.y);
        hu[2] = relu_(ps.z + qd.z + bb.z);
        hu[3] = relu_(ps.w + qd.w + bb.w);
        hw[0] = relu_(pd.x + qs.x + bb.x);
        hw[1] = relu_(pd.y + qs.y + bb.y);
        hw[2] = relu_(pd.z + qs.z + bb.z);
        hw[3] = relu_(pd.w + qs.w + bb.w);
#pragma unroll
        for (int jj = 0; jj < 4; jj++) {
            // this thread's hidden unit j = 16k + 4t + jj; its W2 row in
            // permuted layout at float4 index ((k*4+jj)*4 + ic)*4 + t
            int base = ((k * 4 + jj) * 4) * 4 + t;
            float4 w0  = w2v4[base];
            float4 w1  = w2v4[base + 4];
            float4 w2q = w2v4[base + 8];
            float4 w3  = w2v4[base + 12];
            float a = hu[jj], b = hw[jj];
            pu[0]  = fmaf(w0.x, a, pu[0]);  pw[0]  = fmaf(w0.x, b, pw[0]);
            pu[1]  = fmaf(w0.y, a, pu[1]);  pw[1]  = fmaf(w0.y, b, pw[1]);
            pu[2]  = fmaf(w0.z, a, pu[2]);  pw[2]  = fmaf(w0.z, b, pw[2]);
            pu[3]  = fmaf(w0.w, a, pu[3]);  pw[3]  = fmaf(w0.w, b, pw[3]);
            pu[4]  = fmaf(w1.x, a, pu[4]);  pw[4]  = fmaf(w1.x, b, pw[4]);
            pu[5]  = fmaf(w1.y, a, pu[5]);  pw[5]  = fmaf(w1.y, b, pw[5]);
            pu[6]  = fmaf(w1.z, a, pu[6]);  pw[6]  = fmaf(w1.z, b, pw[6]);
            pu[7]  = fmaf(w1.w, a, pu[7]);  pw[7]  = fmaf(w1.w, b, pw[7]);
            pu[8]  = fmaf(w2q.x, a, pu[8]); pw[8]  = fmaf(w2q.x, b, pw[8]);
            pu[9]  = fmaf(w2q.y, a, pu[9]); pw[9]  = fmaf(w2q.y, b, pw[9]);
            pu[10] = fmaf(w2q.z, a, pu[10]); pw[10] = fmaf(w2q.z, b, pw[10]);
            pu[11] = fmaf(w2q.w, a, pu[11]); pw[11] = fmaf(w2q.w, b, pw[11]);
            pu[12] = fmaf(w3.x, a, pu[12]); pw[12] = fmaf(w3.x, b, pw[12]);
            pu[13] = fmaf(w3.y, a, pu[13]); pw[13] = fmaf(w3.y, b, pw[13]);
            pu[14] = fmaf(w3.z, a, pu[14]); pw[14] = fmaf(w3.z, b, pw[14]);
            pu[15] = fmaf(w3.w, a, pu[15]); pw[15] = fmaf(w3.w, b, pw[15]);
        }
    }

    // ---- reduction round 1 (xor 2), select-send: 16 SHFL ----
    float qu[8], qw[8];
    {
        bool hi = (lane & 2) != 0;
#pragma unroll
        for (int i = 0; i < 8; i++) {
            float su = hi ? pu[i] : pu[i + 8];
            float ru = __shfl_xor_sync(0xffffffffu, su, 2);
            qu[i] = (hi ? pu[i + 8] : pu[i]) + ru;
            float sw = hi ? pw[i] : pw[i + 8];
            float rw = __shfl_xor_sync(0xffffffffu, sw, 2);
            qw[i] = (hi ? pw[i + 8] : pw[i]) + rw;
        }
    }
    // ---- reduction round 2 (xor 1): thread t owns dims [4t,4t+4) ----
    float fu[4], fw[4];
    {
        bool hi = (lane & 1) != 0;
#pragma unroll
        for (int i = 0; i < 4; i++) {
            float su = hi ? qu[i] : qu[i + 4];
            float ru = __shfl_xor_sync(0xffffffffu, su, 1);
            fu[i] = (hi ? qu[i + 4] : qu[i]) + ru;
            float sw = hi ? qw[i] : qw[i + 4];
            float rw = __shfl_xor_sync(0xffffffffu, sw, 1);
            fw[i] = (hi ? qw[i + 4] : qw[i]) + rw;
        }
    }
#pragma unroll
    for (int i = 0; i < 4; i++) {
        float b2i = b2s[4 * t + i];
        fu[i] += b2i;
        fw[i] += b2i;
    }

    // own slice of x (quad lanes contiguous 64B per edge)
    float xso[4], xdo[4];
    {
        float4 a = *(const float4*)(x + (size_t)s * D + 4 * t);
        float4 b = *(const float4*)(x + (size_t)d * D + 4 * t);
        xso[0] = a.x; xso[1] = a.y; xso[2] = a.z; xso[3] = a.w;
        xdo[0] = b.x; xdo[1] = b.y; xdo[2] = b.z; xdo[3] = b.w;
    }

    // 7 partial dots over own dims, reduce across quad
    float n2u = 0.f, n2w = 0.f, puw = 0.f, pu_xd = 0.f, pw_xd = 0.f, pu_xs = 0.f, pw_xs = 0.f;
#pragma unroll
    for (int i = 0; i < 4; i++) {
        n2u   = fmaf(fu[i], fu[i],  n2u);
        n2w   = fmaf(fw[i], fw[i],  n2w);
        puw   = fmaf(fu[i], fw[i],  puw);
        pu_xd = fmaf(fu[i], xdo[i], pu_xd);
        pw_xd = fmaf(fw[i], xdo[i], pw_xd);
        pu_xs = fmaf(fu[i], xso[i], pu_xs);
        pw_xs = fmaf(fw[i], xso[i], pw_xs);
    }
#pragma unroll
    for (int m = 1; m <= 2; m <<= 1) {
        n2u   += __shfl_xor_sync(0xffffffffu, n2u,   m);
        n2w   += __shfl_xor_sync(0xffffffffu, n2w,   m);
        puw   += __shfl_xor_sync(0xffffffffu, puw,   m);
        pu_xd += __shfl_xor_sync(0xffffffffu, pu_xd, m);
        pw_xd += __shfl_xor_sync(0xffffffffu, pw_xd, m);
        pu_xs += __shfl_xor_sync(0xffffffffu, pu_xs, m);
        pw_xs += __shfl_xor_sync(0xffffffffu, pw_xs, m);
    }

    float invu = 1.0f / fmaxf(sqrtf(n2u), 1e-12f);
    float invw = 1.0f / fmaxf(sqrtf(n2w), 1e-12f);

    float uw   = puw   * invu * invw;
    float u_xd = pu_xd * invu;
    float w_xd = pw_xd * invw;
    float u_xs = pu_xs * invu;
    float w_xs = pw_xs * invw;

    float coef = rsqrtf(fmaxf(g_deg[s], 1e-5f)) * rsqrtf(fmaxf(g_deg[d], 1e-5f));

    // F_s = I-2uu^T, F_d = I-2ww^T, L = -F_s^T F_d (coefficients act on raw fu/fw)
    float cu_s = (-2.0f * u_xd + 4.0f * uw * w_xd) * invu;
    float cw_s = (-2.0f * w_xd) * invw;
    float cu_d = (-2.0f * u_xs) * invu;
    float cw_d = (-2.0f * w_xs + 4.0f * uw * u_xs) * invw;

    if (valid) {
        float ms[4], md[4];
#pragma unroll
        for (int i = 0; i < 4; i++) {
            ms[i] = -coef * (xdo[i] + cu_s * fu[i] + cw_s * fw[i]);
            md[i] = -coef * (xso[i] + cu_d * fu[i] + cw_d * fw[i]);
        }
        red_add_v4(&g_acc[(size_t)s * D + 4 * t], ms[0], ms[1], ms[2], ms[3]);
        red_add_v4(&g_acc[(size_t)d * D + 4 * t], md[0], md[1], md[2], md[3]);
    }
}

__global__ void out_kernel(const float* __restrict__ x, float* __restrict__ out, int n) {
    int idx = blockIdx.x * blockDim.x + threadIdx.x;
    if (idx >= n) return;
    out[idx] = fmaxf(x[idx] - g_acc[idx], 0.0f);
}

extern "C" void kernel_launch(void* const* d_in, const int* in_sizes, int n_in,
                              void* d_out, int out_size) {
    const float* x  = (const float*)d_in[0];
    const int*   ei = (const int*)d_in[1];   // edge_index is int32 (JAX x64 disabled)
    const float* W1 = (const float*)d_in[2];
    const float* b1 = (const float*)d_in[3];
    const float* W2 = (const float*)d_in[4];
    const float* b2 = (const float*)d_in[5];
    float* out = (float*)d_out;

    int E = in_sizes[1] / 2;
    int n = in_sizes[0];
    int n_nodes = n / D;

    int initTotal = N_NODES * D + N_NODES;
    init_kernel<<<(initTotal + 255) / 256, 256>>>();
    deg_kernel<<<(E + 255) / 256, 256>>>(ei, E);
    node_kernel<<<(n_nodes + 127) / 128, 128>>>(x, W1, n_nodes);

    // 4 threads per edge, 8 edges per warp, 64 edges per 256-thread block
    int blocks = (E + 63) / 64;
    edge_kernel<<<blocks, 256>>>(x, ei, b1, W2, b2, E);

    out_kernel<<<(n + 255) / 256, 256>>>(x, out, n);
}

// round 9
// speedup vs baseline: 1.9425x; 1.0112x over previous
#include <cuda_runtime.h>
#include <cuda_bf16.h>

#define N_NODES 50000
#define D 16
#define H 64
#define RECSZ 160          // floats per node record: P[64] Q[64] x[16] rsd pad
#define TILE 128
#define BLOCK 128

__device__ float g_acc[N_NODES * D];
__device__ float g_deg[N_NODES];
__device__ float g_rec[N_NODES * RECSZ];   // 32 MB

typedef unsigned long long u64c;
__device__ __forceinline__ u64c pack2(float a, float b) {
    u64c r; asm("mov.b64 %0, {%1, %2};" : "=l"(r) : "f"(a), "f"(b)); return r;
}
__device__ __forceinline__ void unpack2(u64c v, float& a, float& b) {
    asm("mov.b64 {%0, %1}, %2;" : "=f"(a), "=f"(b) : "l"(v));
}
__device__ __forceinline__ void ffma2(u64c& acc, u64c w, u64c h) {
    asm("fma.rn.f32x2 %0, %1, %2, %0;" : "+l"(acc) : "l"(w), "l"(h));
}
__device__ __forceinline__ void red_add_v4(float* addr, float a, float b, float c, float d) {
    asm volatile("red.global.add.v4.f32 [%0], {%1, %2, %3, %4};"
                 :: "l"(addr), "f"(a), "f"(b), "f"(c), "f"(d) : "memory");
}
__device__ __forceinline__ float relu_(float v) { return fmaxf(v, 0.0f); }

__global__ void init_kernel() {
    int idx = blockIdx.x * blockDim.x + threadIdx.x;
    int total = N_NODES * D + N_NODES;
    if (idx < N_NODES * D) g_acc[idx] = 0.0f;
    else if (idx < total)  g_deg[idx - N_NODES * D] = 0.0f;
}

__global__ void deg_kernel(const int* __restrict__ ei, int E) {
    int e = blockIdx.x * blockDim.x + threadIdx.x;
    if (e >= E) return;
    atomicAdd(&g_deg[ei[e]], 1.0f);
    atomicAdd(&g_deg[ei[E + e]], 1.0f);
}

// Per node: record = [ P=W1a@x (64) | Q=W1b@x (64) | x (16) | rsd | pad ]
__global__ __launch_bounds__(128)
void node_kernel(const float* __restrict__ x, const float* __restrict__ W1, int n_nodes)
{
    __shared__ float w1s[H * 32];
    for (int i = threadIdx.x; i < H * 32; i += blockDim.x) w1s[i] = W1[i];
    __syncthreads();

    int n = blockIdx.x * blockDim.x + threadIdx.x;
    if (n >= n_nodes) return;

    float xv[D];
    const float4* px = (const float4*)(x + (size_t)n * D);
#pragma unroll
    for (int q = 0; q < 4; q++) {
        float4 v4 = px[q];
        xv[4 * q + 0] = v4.x; xv[4 * q + 1] = v4.y;
        xv[4 * q + 2] = v4.z; xv[4 * q + 3] = v4.w;
    }

    float* rec = &g_rec[(size_t)n * RECSZ];
#pragma unroll 4
    for (int jg = 0; jg < H / 4; jg++) {
        float p[4], qv[4];
#pragma unroll
        for (int jj = 0; jj < 4; jj++) {
            const float* w = &w1s[(jg * 4 + jj) * 32];
            float p0 = 0.f, p1 = 0.f, q0 = 0.f, q1 = 0.f;
#pragma unroll
            for (int k = 0; k < D; k += 2) {
                p0 = fmaf(w[k],          xv[k],     p0);
                p1 = fmaf(w[k + 1],      xv[k + 1], p1);
                q0 = fmaf(w[16 + k],     xv[k],     q0);
                q1 = fmaf(w[16 + k + 1], xv[k + 1], q1);
            }
            p[jj] = p0 + p1;
            qv[jj] = q0 + q1;
        }
        *(float4*)(rec + jg * 4)     = make_float4(p[0], p[1], p[2], p[3]);
        *(float4*)(rec + H + jg * 4) = make_float4(qv[0], qv[1], qv[2], qv[3]);
    }
#pragma unroll
    for (int q = 0; q < 4; q++)
        *(float4*)(rec + 2 * H + 4 * q) = px[q];
    rec[2 * H + D] = rsqrtf(fmaxf(g_deg[n], 1e-5f));
}

// SMEM layout (dynamic):
//  hu[TILE][65], hw[TILE][65], w2s[64*16], b1s4[16 float4], b2s[16], eis[TILE], eid[TILE]
#define HU_STRIDE 65

__global__ __launch_bounds__(BLOCK)
void edge_kernel(const int* __restrict__ ei,
                 const float* __restrict__ b1, const float* __restrict__ W2,
                 const float* __restrict__ b2, int E)
{
    extern __shared__ float smem[];
    float* hu   = smem;                         // TILE*65
    float* hw   = hu + TILE * HU_STRIDE;        // TILE*65
    float* w2s  = hw + TILE * HU_STRIDE;        // 1024
    float* b1sf = w2s + H * D;                  // 64
    float* b2s  = b1sf + H;                     // 16
    int*   eis  = (int*)(b2s + D);              // TILE
    int*   eid  = eis + TILE;                   // TILE

    const float* __restrict__ rec = g_rec;

    int tid = threadIdx.x;
    int e0 = blockIdx.x * TILE;

    // ---- init loads ----
    for (int i = tid; i < H * D; i += BLOCK) {
        int j = i >> 4, ii = i & 15;
        w2s[i] = W2[ii * H + j];                 // w2s[j][i] = W2[i][j]
    }
    if (tid < H) b1sf[tid] = b1[tid];
    if (tid < D) b2s[tid] = b2[tid];
    {
        int eg = e0 + tid; if (eg >= E) eg = E - 1;
        eis[tid] = ei[eg];
        eid[tid] = ei[E + eg];
    }
    __syncthreads();

    // ---- phase 1: coalesced gather + stage hu/hw ----
    {
        int lane = tid & 31, w = tid >> 5;
        int half = lane >> 4, cl = lane & 15;
        float4 bb = ((const float4*)b1sf)[cl];
#pragma unroll 4
        for (int it = 0; it < 16; it++) {
            int eL = it * 8 + (w << 1) + half;
            int s = eis[eL], d = eid[eL];
            const float* rs = rec + s * RECSZ;
            const float* rd = rec + d * RECSZ;
            float4 ps = *(const float4*)(rs + 4 * cl);
            float4 qd = *(const float4*)(rd + H + 4 * cl);
            float4 pd = *(const float4*)(rd + 4 * cl);
            float4 qs = *(const float4*)(rs + H + 4 * cl);
            float hu0 = relu_(ps.x + qd.x + bb.x);
            float hu1 = relu_(ps.y + qd.y + bb.y);
            float hu2 = relu_(ps.z + qd.z + bb.z);
            float hu3 = relu_(ps.w + qd.w + bb.w);
            float hw0 = relu_(pd.x + qs.x + bb.x);
            float hw1 = relu_(pd.y + qs.y + bb.y);
            float hw2 = relu_(pd.z + qs.z + bb.z);
            float hw3 = relu_(pd.w + qs.w + bb.w);
            float* pu = &hu[eL * HU_STRIDE + 4 * cl];
            float* pw = &hw[eL * HU_STRIDE + 4 * cl];
            pu[0] = hu0; pu[1] = hu1; pu[2] = hu2; pu[3] = hu3;
            pw[0] = hw0; pw[1] = hw1; pw[2] = hw2; pw[3] = hw3;
        }
    }
    __syncthreads();

    // ---- phase 2: thread-per-edge layer-2 (f32x2) + epilogue ----
    int eL = tid;
    bool valid = (e0 + eL < E);
    int s = eis[eL], d = eid[eL];

    const float* hue = &hu[eL * HU_STRIDE];
    const float* hwe = &hw[eL * HU_STRIDE];

    u64c vu2[8], vw2[8];
#pragma unroll
    for (int k = 0; k < 8; k++) {
        u64c b = pack2(b2s[2 * k], b2s[2 * k + 1]);
        vu2[k] = b; vw2[k] = b;
    }

#pragma unroll 8
    for (int j = 0; j < H; j++) {
        float hj = hue[j], gj = hwe[j];
        u64c h2 = pack2(hj, hj);
        u64c g2 = pack2(gj, gj);
        const float4* wr = (const float4*)&w2s[j * D];
        float4 w0 = wr[0], w1 = wr[1], w2q = wr[2], w3 = wr[3];
        u64c a0 = pack2(w0.x,  w0.y),  a1 = pack2(w0.z,  w0.w);
        u64c a2 = pack2(w1.x,  w1.y),  a3 = pack2(w1.z,  w1.w);
        u64c a4 = pack2(w2q.x, w2q.y), a5 = pack2(w2q.z, w2q.w);
        u64c a6 = pack2(w3.x,  w3.y),  a7 = pack2(w3.z,  w3.w);
        ffma2(vu2[0], a0, h2); ffma2(vw2[0], a0, g2);
        ffma2(vu2[1], a1, h2); ffma2(vw2[1], a1, g2);
        ffma2(vu2[2], a2, h2); ffma2(vw2[2], a2, g2);
        ffma2(vu2[3], a3, h2); ffma2(vw2[3], a3, g2);
        ffma2(vu2[4], a4, h2); ffma2(vw2[4], a4, g2);
        ffma2(vu2[5], a5, h2); ffma2(vw2[5], a5, g2);
        ffma2(vu2[6], a6, h2); ffma2(vw2[6], a6, g2);
        ffma2(vu2[7], a7, h2); ffma2(vw2[7], a7, g2);
    }

    float fu[16], fw[16];
#pragma unroll
    for (int k = 0; k < 8; k++) {
        unpack2(vu2[k], fu[2 * k], fu[2 * k + 1]);
        unpack2(vw2[k], fw[2 * k], fw[2 * k + 1]);
    }

    const float* rs = rec + s * RECSZ;
    const float* rd = rec + d * RECSZ;
    float xs[16], xd[16];
#pragma unroll
    for (int q = 0; q < 4; q++) {
        float4 a = *(const float4*)(rs + 2 * H + 4 * q);
        float4 b = *(const float4*)(rd + 2 * H + 4 * q);
        xs[4 * q + 0] = a.x; xs[4 * q + 1] = a.y; xs[4 * q + 2] = a.z; xs[4 * q + 3] = a.w;
        xd[4 * q + 0] = b.x; xd[4 * q + 1] = b.y; xd[4 * q + 2] = b.z; xd[4 * q + 3] = b.w;
    }
    float coef = rs[2 * H + D] * rd[2 * H + D];

    float n2u = 0.f, n2w = 0.f, puw = 0.f, pu_xd = 0.f, pw_xd = 0.f, pu_xs = 0.f, pw_xs = 0.f;
#pragma unroll
    for (int i = 0; i < 16; i++) {
        n2u   = fmaf(fu[i], fu[i], n2u);
        n2w   = fmaf(fw[i], fw[i], n2w);
        puw   = fmaf(fu[i], fw[i], puw);
        pu_xd = fmaf(fu[i], xd[i], pu_xd);
        pw_xd = fmaf(fw[i], xd[i], pw_xd);
        pu_xs = fmaf(fu[i], xs[i], pu_xs);
        pw_xs = fmaf(fw[i], xs[i], pw_xs);
    }

    float invu = 1.0f / fmaxf(sqrtf(n2u), 1e-12f);
    float invw = 1.0f / fmaxf(sqrtf(n2w), 1e-12f);

    float uw   = puw   * invu * invw;
    float u_xd = pu_xd * invu;
    float w_xd = pw_xd * invw;
    float u_xs = pu_xs * invu;
    float w_xs = pw_xs * invw;

    // F_s = I-2uu^T, F_d = I-2ww^T, L = -F_s^T F_d ; coefficients act on raw fu/fw
    float cu_s = (-2.0f * u_xd + 4.0f * uw * w_xd) * invu;
    float cw_s = (-2.0f * w_xd) * invw;
    float cu_d = (-2.0f * u_xs) * invu;
    float cw_d = (-2.0f * w_xs + 4.0f * uw * u_xs) * invw;

    if (valid) {
        float* accs = &g_acc[(size_t)s * D];
        float* accd = &g_acc[(size_t)d * D];
#pragma unroll
        for (int q = 0; q < 4; q++) {
            float m0 = -coef * (xd[4*q+0] + cu_s * fu[4*q+0] + cw_s * fw[4*q+0]);
            float m1 = -coef * (xd[4*q+1] + cu_s * fu[4*q+1] + cw_s * fw[4*q+1]);
            float m2 = -coef * (xd[4*q+2] + cu_s * fu[4*q+2] + cw_s * fw[4*q+2]);
            float m3 = -coef * (xd[4*q+3] + cu_s * fu[4*q+3] + cw_s * fw[4*q+3]);
            red_add_v4(accs + 4 * q, m0, m1, m2, m3);
        }
#pragma unroll
        for (int q = 0; q < 4; q++) {
            float m0 = -coef * (xs[4*q+0] + cu_d * fu[4*q+0] + cw_d * fw[4*q+0]);
            float m1 = -coef * (xs[4*q+1] + cu_d * fu[4*q+1] + cw_d * fw[4*q+1]);
            float m2 = -coef * (xs[4*q+2] + cu_d * fu[4*q+2] + cw_d * fw[4*q+2]);
            float m3 = -coef * (xs[4*q+3] + cu_d * fu[4*q+3] + cw_d * fw[4*q+3]);
            red_add_v4(accd + 4 * q, m0, m1, m2, m3);
        }
    }
}

__global__ void out_kernel(const float* __restrict__ x, float* __restrict__ out, int n) {
    int idx = blockIdx.x * blockDim.x + threadIdx.x;
    if (idx >= n) return;
    out[idx] = fmaxf(x[idx] - g_acc[idx], 0.0f);
}

extern "C" void kernel_launch(void* const* d_in, const int* in_sizes, int n_in,
                              void* d_out, int out_size) {
    const float* x  = (const float*)d_in[0];
    const int*   ei = (const int*)d_in[1];   // edge_index is int32 (JAX x64 disabled)
    const float* W1 = (const float*)d_in[2];
    const float* b1 = (const float*)d_in[3];
    const float* W2 = (const float*)d_in[4];
    const float* b2 = (const float*)d_in[5];
    float* out = (float*)d_out;

    int E = in_sizes[1] / 2;
    int n = in_sizes[0];
    int n_nodes = n / D;

    // dynamic smem: hu + hw + w2 + b1 + b2 + ei*2
    size_t smemBytes = (2 * TILE * HU_STRIDE + H * D + H + D) * sizeof(float)
                     + 2 * TILE * sizeof(int);
    cudaFuncSetAttribute(edge_kernel, cudaFuncAttributeMaxDynamicSharedMemorySize,
                         (int)smemBytes);

    int initTotal = N_NODES * D + N_NODES;
    init_kernel<<<(initTotal + 255) / 256, 256>>>();
    deg_kernel<<<(E + 255) / 256, 256>>>(ei, E);
    node_kernel<<<(n_nodes + 127) / 128, 128>>>(x, W1, n_nodes);

    int nTiles = (E + TILE - 1) / TILE;
    edge_kernel<<<nTiles, BLOCK, smemBytes>>>(ei, b1, W2, b2, E);

    out_kernel<<<(n + 255) / 256, 256>>>(x, out, n);
}

// round 11
// speedup vs baseline: 2.0858x; 1.0738x over previous
#include <cuda_runtime.h>
#include <cuda_bf16.h>
#include <cuda_fp16.h>

#define N_NODES 50000
#define D 16
#define H 64
#define RECSZ 160          // floats per node record: P[64] Q[64] x[16] rsd pad
#define TILE 256
#define BLOCK 256
#define HUW_STRIDE 65      // uint32 units per edge row (odd -> conflict-free)

__device__ float g_acc[N_NODES * D];
__device__ float g_deg[N_NODES];
__device__ float g_rec[N_NODES * RECSZ];   // 32 MB

typedef unsigned long long u64c;
__device__ __forceinline__ u64c pack2(float a, float b) {
    u64c r; asm("mov.b64 %0, {%1, %2};" : "=l"(r) : "f"(a), "f"(b)); return r;
}
__device__ __forceinline__ void unpack2(u64c v, float& a, float& b) {
    asm("mov.b64 {%0, %1}, %2;" : "=f"(a), "=f"(b) : "l"(v));
}
__device__ __forceinline__ void ffma2(u64c& acc, u64c w, u64c h) {
    asm("fma.rn.f32x2 %0, %1, %2, %0;" : "+l"(acc) : "l"(w), "l"(h));
}
__device__ __forceinline__ void red_add_v4(float* addr, float a, float b, float c, float d) {
    asm volatile("red.global.add.v4.f32 [%0], {%1, %2, %3, %4};"
                 :: "l"(addr), "f"(a), "f"(b), "f"(c), "f"(d) : "memory");
}
__device__ __forceinline__ float relu_(float v) { return fmaxf(v, 0.0f); }
__device__ __forceinline__ unsigned h2_bits(__half2 h) {
    return *reinterpret_cast<unsigned*>(&h);
}

__global__ void init_kernel() {
    int idx = blockIdx.x * blockDim.x + threadIdx.x;
    int total = N_NODES * D + N_NODES;
    if (idx < N_NODES * D) g_acc[idx] = 0.0f;
    else if (idx < total)  g_deg[idx - N_NODES * D] = 0.0f;
}

__global__ void deg_kernel(const int* __restrict__ ei, int E) {
    int e = blockIdx.x * blockDim.x + threadIdx.x;
    if (e >= E) return;
    atomicAdd(&g_deg[ei[e]], 1.0f);
    atomicAdd(&g_deg[ei[E + e]], 1.0f);
}

// Per node: record = [ P=W1a@x (64) | Q=W1b@x (64) | x (16) | rsd | pad ]
__global__ __launch_bounds__(128)
void node_kernel(const float* __restrict__ x, const float* __restrict__ W1, int n_nodes)
{
    __shared__ float w1s[H * 32];
    for (int i = threadIdx.x; i < H * 32; i += blockDim.x) w1s[i] = W1[i];
    __syncthreads();

    int n = blockIdx.x * blockDim.x + threadIdx.x;
    if (n >= n_nodes) return;

    float xv[D];
    const float4* px = (const float4*)(x + (size_t)n * D);
#pragma unroll
    for (int q = 0; q < 4; q++) {
        float4 v4 = px[q];
        xv[4 * q + 0] = v4.x; xv[4 * q + 1] = v4.y;
        xv[4 * q + 2] = v4.z; xv[4 * q + 3] = v4.w;
    }

    float* rec = &g_rec[(size_t)n * RECSZ];
#pragma unroll 4
    for (int jg = 0; jg < H / 4; jg++) {
        float p[4], qv[4];
#pragma unroll
        for (int jj = 0; jj < 4; jj++) {
            const float* w = &w1s[(jg * 4 + jj) * 32];
            float p0 = 0.f, p1 = 0.f, q0 = 0.f, q1 = 0.f;
#pragma unroll
            for (int k = 0; k < D; k += 2) {
                p0 = fmaf(w[k],          xv[k],     p0);
                p1 = fmaf(w[k + 1],      xv[k + 1], p1);
                q0 = fmaf(w[16 + k],     xv[k],     q0);
                q1 = fmaf(w[16 + k + 1], xv[k + 1], q1);
            }
            p[jj] = p0 + p1;
            qv[jj] = q0 + q1;
        }
        *(float4*)(rec + jg * 4)     = make_float4(p[0], p[1], p[2], p[3]);
        *(float4*)(rec + H + jg * 4) = make_float4(qv[0], qv[1], qv[2], qv[3]);
    }
#pragma unroll
    for (int q = 0; q < 4; q++)
        *(float4*)(rec + 2 * H + 4 * q) = px[q];
    rec[2 * H + D] = rsqrtf(fmaxf(g_deg[n], 1e-5f));
}

// SMEM: huw[TILE][65] (half2 per j), w2s[64*16], b1s[64], b2s[16], eis/eid[TILE]
__global__ __launch_bounds__(BLOCK, 3)
void edge_kernel(const int* __restrict__ ei,
                 const float* __restrict__ b1, const float* __restrict__ W2,
                 const float* __restrict__ b2, int E)
{
    extern __shared__ float smem[];
    unsigned* huw = (unsigned*)smem;            // TILE*65 uint32 (half2 each)
    float* w2s  = smem + TILE * HUW_STRIDE;     // 1024
    float* b1sf = w2s + H * D;                  // 64
    float* b2s  = b1sf + H;                     // 16
    int*   eis  = (int*)(b2s + D);              // TILE
    int*   eid  = eis + TILE;                   // TILE

    const float* __restrict__ rec = g_rec;

    int tid = threadIdx.x;
    int e0 = blockIdx.x * TILE;

    // ---- init loads ----
    for (int i = tid; i < H * D; i += BLOCK) {
        int j = i >> 4, ii = i & 15;
        w2s[i] = W2[ii * H + j];                 // w2s[j][i] = W2[i][j]
    }
    if (tid < H) b1sf[tid] = b1[tid];
    if (tid < D) b2s[tid] = b2[tid];
    {
        int eg = e0 + tid; if (eg >= E) eg = E - 1;
        eis[tid] = ei[eg];
        eid[tid] = ei[E + eg];
    }
    __syncthreads();

    // ---- phase 1: coalesced gather + stage half2(hu,hw) ----
    {
        int lane = tid & 31, w = tid >> 5;       // 8 warps
        int half = lane >> 4, cl = lane & 15;
        float4 bb = ((const float4*)b1sf)[cl];
#pragma unroll 4
        for (int it = 0; it < TILE / 16; it++) {
            int eL = it * 16 + (w << 1) + half;
            int s = eis[eL], d = eid[eL];
            const float* rs = rec + s * RECSZ;
            const float* rd = rec + d * RECSZ;
            float4 ps = *(const float4*)(rs + 4 * cl);
            float4 qd = *(const float4*)(rd + H + 4 * cl);
            float4 pd = *(const float4*)(rd + 4 * cl);
            float4 qs = *(const float4*)(rs + H + 4 * cl);
            __half2 h0 = __floats2half2_rn(relu_(ps.x + qd.x + bb.x), relu_(pd.x + qs.x + bb.x));
            __half2 h1 = __floats2half2_rn(relu_(ps.y + qd.y + bb.y), relu_(pd.y + qs.y + bb.y));
            __half2 h2 = __floats2half2_rn(relu_(ps.z + qd.z + bb.z), relu_(pd.z + qs.z + bb.z));
            __half2 h3 = __floats2half2_rn(relu_(ps.w + qd.w + bb.w), relu_(pd.w + qs.w + bb.w));
            unsigned* row = &huw[eL * HUW_STRIDE + 4 * cl];
            row[0] = h2_bits(h0);
            row[1] = h2_bits(h1);
            row[2] = h2_bits(h2);
            row[3] = h2_bits(h3);
        }
    }
    __syncthreads();

    // ---- phase 2: thread-per-edge layer-2 (f32x2) + epilogue ----
    int eL = tid;
    bool valid = (e0 + eL < E);
    int s = eis[eL], d = eid[eL];

    const unsigned* he = &huw[eL * HUW_STRIDE];

    u64c vu2[8], vw2[8];
#pragma unroll
    for (int k = 0; k < 8; k++) {
        u64c b = pack2(b2s[2 * k], b2s[2 * k + 1]);
        vu2[k] = b; vw2[k] = b;
    }

#pragma unroll 8
    for (int j = 0; j < H; j++) {
        unsigned raw = he[j];
        __half2 hraw = *reinterpret_cast<__half2*>(&raw);
        float2 hg = __half22float2(hraw);                    // (hu_j, hw_j)
        u64c h2 = pack2(hg.x, hg.x);
        u64c g2 = pack2(hg.y, hg.y);
        const float4* wr = (const float4*)&w2s[j * D];
        float4 w0 = wr[0], w1 = wr[1], w2q = wr[2], w3 = wr[3];
        u64c a0 = pack2(w0.x,  w0.y),  a1 = pack2(w0.z,  w0.w);
        u64c a2 = pack2(w1.x,  w1.y),  a3 = pack2(w1.z,  w1.w);
        u64c a4 = pack2(w2q.x, w2q.y), a5 = pack2(w2q.z, w2q.w);
        u64c a6 = pack2(w3.x,  w3.y),  a7 = pack2(w3.z,  w3.w);
        ffma2(vu2[0], a0, h2); ffma2(vw2[0], a0, g2);
        ffma2(vu2[1], a1, h2); ffma2(vw2[1], a1, g2);
        ffma2(vu2[2], a2, h2); ffma2(vw2[2], a2, g2);
        ffma2(vu2[3], a3, h2); ffma2(vw2[3], a3, g2);
        ffma2(vu2[4], a4, h2); ffma2(vw2[4], a4, g2);
        ffma2(vu2[5], a5, h2); ffma2(vw2[5], a5, g2);
        ffma2(vu2[6], a6, h2); ffma2(vw2[6], a6, g2);
        ffma2(vu2[7], a7, h2); ffma2(vw2[7], a7, g2);
    }

    float fu[16], fw[16];
#pragma unroll
    for (int k = 0; k < 8; k++) {
        unpack2(vu2[k], fu[2 * k], fu[2 * k + 1]);
        unpack2(vw2[k], fw[2 * k], fw[2 * k + 1]);
    }

    const float* rs = rec + s * RECSZ;
    const float* rd = rec + d * RECSZ;
    float xs[16], xd[16];
#pragma unroll
    for (int q = 0; q < 4; q++) {
        float4 a = *(const float4*)(rs + 2 * H + 4 * q);
        float4 b = *(const float4*)(rd + 2 * H + 4 * q);
        xs[4 * q + 0] = a.x; xs[4 * q + 1] = a.y; xs[4 * q + 2] = a.z; xs[4 * q + 3] = a.w;
        xd[4 * q + 0] = b.x; xd[4 * q + 1] = b.y; xd[4 * q + 2] = b.z; xd[4 * q + 3] = b.w;
    }
    float coef = rs[2 * H + D] * rd[2 * H + D];

    float n2u = 0.f, n2w = 0.f, puw = 0.f, pu_xd = 0.f, pw_xd = 0.f, pu_xs = 0.f, pw_xs = 0.f;
#pragma unroll
    for (int i = 0; i < 16; i++) {
        n2u   = fmaf(fu[i], fu[i], n2u);
        n2w   = fmaf(fw[i], fw[i], n2w);
        puw   = fmaf(fu[i], fw[i], puw);
        pu_xd = fmaf(fu[i], xd[i], pu_xd);
        pw_xd = fmaf(fw[i], xd[i], pw_xd);
        pu_xs = fmaf(fu[i], xs[i], pu_xs);
        pw_xs = fmaf(fw[i], xs[i], pw_xs);
    }

    float invu = 1.0f / fmaxf(sqrtf(n2u), 1e-12f);
    float invw = 1.0f / fmaxf(sqrtf(n2w), 1e-12f);

    float uw   = puw   * invu * invw;
    float u_xd = pu_xd * invu;
    float w_xd = pw_xd * invw;
    float u_xs = pu_xs * invu;
    float w_xs = pw_xs * invw;

    // F_s = I-2uu^T, F_d = I-2ww^T, L = -F_s^T F_d ; coefficients act on raw fu/fw
    float cu_s = (-2.0f * u_xd + 4.0f * uw * w_xd) * invu;
    float cw_s = (-2.0f * w_xd) * invw;
    float cu_d = (-2.0f * u_xs) * invu;
    float cw_d = (-2.0f * w_xs + 4.0f * uw * u_xs) * invw;

    if (valid) {
        float* accs = &g_acc[(size_t)s * D];
        float* accd = &g_acc[(size_t)d * D];
#pragma unroll
        for (int q = 0; q < 4; q++) {
            float m0 = -coef * (xd[4*q+0] + cu_s * fu[4*q+0] + cw_s * fw[4*q+0]);
            float m1 = -coef * (xd[4*q+1] + cu_s * fu[4*q+1] + cw_s * fw[4*q+1]);
            float m2 = -coef * (xd[4*q+2] + cu_s * fu[4*q+2] + cw_s * fw[4*q+2]);
            float m3 = -coef * (xd[4*q+3] + cu_s * fu[4*q+3] + cw_s * fw[4*q+3]);
            red_add_v4(accs + 4 * q, m0, m1, m2, m3);
        }
#pragma unroll
        for (int q = 0; q < 4; q++) {
            float m0 = -coef * (xs[4*q+0] + cu_d * fu[4*q+0] + cw_d * fw[4*q+0]);
            float m1 = -coef * (xs[4*q+1] + cu_d * fu[4*q+1] + cw_d * fw[4*q+1]);
            float m2 = -coef * (xs[4*q+2] + cu_d * fu[4*q+2] + cw_d * fw[4*q+2]);
            float m3 = -coef * (xs[4*q+3] + cu_d * fu[4*q+3] + cw_d * fw[4*q+3]);
            red_add_v4(accd + 4 * q, m0, m1, m2, m3);
        }
    }
}

__global__ void out_kernel(const float* __restrict__ x, float* __restrict__ out, int n) {
    int idx = blockIdx.x * blockDim.x + threadIdx.x;
    if (idx >= n) return;
    out[idx] = fmaxf(x[idx] - g_acc[idx], 0.0f);
}

extern "C" void kernel_launch(void* const* d_in, const int* in_sizes, int n_in,
                              void* d_out, int out_size) {
    const float* x  = (const float*)d_in[0];
    const int*   ei = (const int*)d_in[1];   // edge_index is int32 (JAX x64 disabled)
    const float* W1 = (const float*)d_in[2];
    const float* b1 = (const float*)d_in[3];
    const float* W2 = (const float*)d_in[4];
    const float* b2 = (const float*)d_in[5];
    float* out = (float*)d_out;

    int E = in_sizes[1] / 2;
    int n = in_sizes[0];
    int n_nodes = n / D;

    size_t smemBytes = (TILE * HUW_STRIDE + H * D + H + D) * sizeof(float)
                     + 2 * TILE * sizeof(int);
    cudaFuncSetAttribute(edge_kernel, cudaFuncAttributeMaxDynamicSharedMemorySize,
                         (int)smemBytes);

    int initTotal = N_NODES * D + N_NODES;
    init_kernel<<<(initTotal + 255) / 256, 256>>>();
    deg_kernel<<<(E + 255) / 256, 256>>>(ei, E);
    node_kernel<<<(n_nodes + 127) / 128, 128>>>(x, W1, n_nodes);

    int nTiles = (E + TILE - 1) / TILE;
    edge_kernel<<<nTiles, BLOCK, smemBytes>>>(ei, b1, W2, b2, E);

    out_kernel<<<(n + 255) / 256, 256>>>(x, out, n);
}